// round 7
// baseline (speedup 1.0000x reference)
#include <cuda_runtime.h>

// out[i,j] = x0[i,j] * (x_l[i] . w) + b[j] + x_l[i,j]
// B = 65536 rows, DIM = 1024.
// Persistent grid: 1216 blocks (152 SMs x 8), 256 threads, float4/thread.
// Each block loads w/b ONCE into registers, then grid-strides over rows with
// software prefetch of the next row's x_l/x_0 issued before the current
// row's reduction barrier -- a load is always in flight per thread.
// Double-buffered warp-sum scratch avoids a second barrier per row.

#define DIM 1024
#define THREADS 256          // DIM/4
#define NBLOCKS (152 * 8)    // GB300: 152 SMs, 8 CTAs/SM at 256 thr

__global__ __launch_bounds__(THREADS) void dcn_kernel(
    const float* __restrict__ x_l,
    const float* __restrict__ x_0,
    const float* __restrict__ w,
    const float* __restrict__ b,
    float* __restrict__ out,
    int nrows)
{
    const int t = threadIdx.x;

    const float4* __restrict__ xl4 = reinterpret_cast<const float4*>(x_l);
    const float4* __restrict__ x04 = reinterpret_cast<const float4*>(x_0);
    float4* __restrict__ out4      = reinterpret_cast<float4*>(out);

    // Per-block invariants: loaded once, live in registers for all rows.
    const float4 wv = reinterpret_cast<const float4*>(w)[t];
    const float4 bv = reinterpret_cast<const float4*>(b)[t];

    __shared__ float warpsum[2][THREADS / 32];

    int row = blockIdx.x;
    if (row >= nrows) return;

    // Prime the pipeline: first row's loads.
    size_t base = (size_t)row * (DIM / 4) + t;
    float4 a = xl4[base];
    float4 c = x04[base];

    int buf = 0;
    while (true) {
        const int next = row + gridDim.x;
        const bool has_next = next < nrows;

        // Prefetch next row's streams BEFORE this row's barrier.
        float4 an, cn;
        size_t nbase = (size_t)next * (DIM / 4) + t;
        if (has_next) {
            an = xl4[nbase];
            cn = x04[nbase];
        }

        // Dot-product partial + reduction for current row.
        float local = a.x * wv.x + a.y * wv.y + a.z * wv.z + a.w * wv.w;
        #pragma unroll
        for (int off = 16; off > 0; off >>= 1)
            local += __shfl_xor_sync(0xffffffffu, local, off);

        if ((t & 31) == 0) warpsum[buf][t >> 5] = local;
        __syncthreads();

        float s = 0.0f;
        #pragma unroll
        for (int i = 0; i < THREADS / 32; i++) s += warpsum[buf][i];

        // Epilogue for current row (all operands in registers).
        float4 o;
        o.x = fmaf(c.x, s, bv.x + a.x);
        o.y = fmaf(c.y, s, bv.y + a.y);
        o.z = fmaf(c.z, s, bv.z + a.z);
        o.w = fmaf(c.w, s, bv.w + a.w);
        out4[base] = o;

        if (!has_next) break;
        row  = next;
        base = nbase;
        a = an;
        c = cn;
        buf ^= 1;   // alternate scratch so no second barrier is needed
    }
}

extern "C" void kernel_launch(void* const* d_in, const int* in_sizes, int n_in,
                              void* d_out, int out_size)
{
    const float* x_l = (const float*)d_in[0];
    const float* x_0 = (const float*)d_in[1];
    const float* w   = (const float*)d_in[2];
    const float* b   = (const float*)d_in[3];
    float* out       = (float*)d_out;

    const int B = in_sizes[0] / DIM;  // 65536
    dcn_kernel<<<NBLOCKS, THREADS>>>(x_l, x_0, w, b, out, B);
}

// round 8
// speedup vs baseline: 1.2509x; 1.2509x over previous
#include <cuda_runtime.h>

// out[i,j] = x0[i,j] * (x_l[i] . w) + b[j] + x_l[i,j]
// B = 65536 rows, DIM = 1024.
// 2 rows per block, 256 threads, float4/thread/row. All four stream loads
// front-batched (MLP_p1=4, 64B in flight per thread); ONE barrier serves
// both rows' dot-product reductions; epilogues are pure register ALU.
// Single-shot blocks (32768) -- block retirement provides the pipelining.

#define DIM 1024
#define THREADS 256  // DIM/4
#define NWARP (THREADS / 32)

__global__ __launch_bounds__(THREADS) void dcn_kernel(
    const float* __restrict__ x_l,
    const float* __restrict__ x_0,
    const float* __restrict__ w,
    const float* __restrict__ b,
    float* __restrict__ out)
{
    const int t = threadIdx.x;
    const size_t r0base = (size_t)(2 * blockIdx.x) * (DIM / 4) + t;
    const size_t r1base = r0base + (DIM / 4);

    const float4* __restrict__ xl4 = reinterpret_cast<const float4*>(x_l);
    const float4* __restrict__ x04 = reinterpret_cast<const float4*>(x_0);
    float4* __restrict__ out4      = reinterpret_cast<float4*>(out);

    // Front-batch everything: 4 stream loads + 2 resident broadcasts.
    float4 a0 = xl4[r0base];
    float4 a1 = xl4[r1base];
    float4 c0 = x04[r0base];
    float4 c1 = x04[r1base];
    const float4 wv = reinterpret_cast<const float4*>(w)[t];
    const float4 bv = reinterpret_cast<const float4*>(b)[t];

    // Partial dots for both rows.
    float l0 = a0.x * wv.x + a0.y * wv.y + a0.z * wv.z + a0.w * wv.w;
    float l1 = a1.x * wv.x + a1.y * wv.y + a1.z * wv.z + a1.w * wv.w;

    // Warp butterfly reduce (both rows interleaved -- independent chains).
    #pragma unroll
    for (int off = 16; off > 0; off >>= 1) {
        l0 += __shfl_xor_sync(0xffffffffu, l0, off);
        l1 += __shfl_xor_sync(0xffffffffu, l1, off);
    }

    __shared__ float warpsum[2][NWARP];
    if ((t & 31) == 0) {
        warpsum[0][t >> 5] = l0;
        warpsum[1][t >> 5] = l1;
    }
    __syncthreads();   // one barrier for both rows

    float s0 = 0.0f, s1 = 0.0f;
    #pragma unroll
    for (int i = 0; i < NWARP; i++) {
        s0 += warpsum[0][i];
        s1 += warpsum[1][i];
    }

    // Register-only epilogues.
    float4 o0, o1;
    o0.x = fmaf(c0.x, s0, bv.x + a0.x);
    o0.y = fmaf(c0.y, s0, bv.y + a0.y);
    o0.z = fmaf(c0.z, s0, bv.z + a0.z);
    o0.w = fmaf(c0.w, s0, bv.w + a0.w);
    o1.x = fmaf(c1.x, s1, bv.x + a1.x);
    o1.y = fmaf(c1.y, s1, bv.y + a1.y);
    o1.z = fmaf(c1.z, s1, bv.z + a1.z);
    o1.w = fmaf(c1.w, s1, bv.w + a1.w);
    out4[r0base] = o0;
    out4[r1base] = o1;
}

extern "C" void kernel_launch(void* const* d_in, const int* in_sizes, int n_in,
                              void* d_out, int out_size)
{
    const float* x_l = (const float*)d_in[0];
    const float* x_0 = (const float*)d_in[1];
    const float* w   = (const float*)d_in[2];
    const float* b   = (const float*)d_in[3];
    float* out       = (float*)d_out;

    const int B = in_sizes[0] / DIM;  // 65536
    dcn_kernel<<<B / 2, THREADS>>>(x_l, x_0, w, b, out);
}

// round 9
// speedup vs baseline: 1.2732x; 1.0178x over previous
#include <cuda_runtime.h>

// out[i,j] = x0[i,j] * (x_l[i] . w) + b[j] + x_l[i,j]
// B = 65536 rows, DIM = 1024.
// FINAL (R4): one block per row, 256 threads, float4 per thread,
// all loads front-batched, default cache ops, one warp-shuffle + shared
// reduction, register-only epilogue. Measured 109.7us kernel / 88.6% DRAM
// (7.02 TB/s) -- the chip's streaming ceiling for this mandatory 768 MB of
// traffic. Seven structural variants (wider MLP, v8 ops, cache hints,
// persistent grid, multi-row blocks) all measured neutral or worse.

#define DIM 1024
#define THREADS 256  // DIM/4

__global__ __launch_bounds__(THREADS) void dcn_kernel(
    const float* __restrict__ x_l,
    const float* __restrict__ x_0,
    const float* __restrict__ w,
    const float* __restrict__ b,
    float* __restrict__ out)
{
    const int row = blockIdx.x;
    const int t   = threadIdx.x;
    const size_t base4 = (size_t)row * (DIM / 4);

    const float4* __restrict__ xl4 = reinterpret_cast<const float4*>(x_l);
    const float4* __restrict__ x04 = reinterpret_cast<const float4*>(x_0);
    const float4* __restrict__ w4  = reinterpret_cast<const float4*>(w);
    const float4* __restrict__ b4  = reinterpret_cast<const float4*>(b);
    float4* __restrict__ out4      = reinterpret_cast<float4*>(out);

    // Front-batch all loads: both DRAM streams in flight together,
    // w/b are 4 KB broadcasts that stay L1/L2 resident.
    float4 a  = xl4[base4 + t];
    float4 c  = x04[base4 + t];
    float4 wv = w4[t];
    float4 bv = b4[t];

    // Partial dot product.
    float local = a.x * wv.x + a.y * wv.y + a.z * wv.z + a.w * wv.w;

    // Warp butterfly reduce.
    #pragma unroll
    for (int off = 16; off > 0; off >>= 1)
        local += __shfl_xor_sync(0xffffffffu, local, off);

    __shared__ float warpsum[THREADS / 32];
    if ((t & 31) == 0) warpsum[t >> 5] = local;
    __syncthreads();

    float s = 0.0f;
    #pragma unroll
    for (int i = 0; i < THREADS / 32; i++) s += warpsum[i];

    // Pure-register epilogue.
    float4 o;
    o.x = fmaf(c.x, s, bv.x + a.x);
    o.y = fmaf(c.y, s, bv.y + a.y);
    o.z = fmaf(c.z, s, bv.z + a.z);
    o.w = fmaf(c.w, s, bv.w + a.w);
    out4[base4 + t] = o;
}

extern "C" void kernel_launch(void* const* d_in, const int* in_sizes, int n_in,
                              void* d_out, int out_size)
{
    const float* x_l = (const float*)d_in[0];
    const float* x_0 = (const float*)d_in[1];
    const float* w   = (const float*)d_in[2];
    const float* b   = (const float*)d_in[3];
    float* out       = (float*)d_out;

    const int B = in_sizes[0] / DIM;  // 65536
    dcn_kernel<<<B, THREADS>>>(x_l, x_0, w, b, out);
}